// round 16
// baseline (speedup 1.0000x reference)
#include <cuda_runtime.h>

typedef unsigned long long u64;
#define WARPS 4
#define PTS 2
#define FULLMASK 0xffffffffu

// constant bank layout (floats):
// [0,192)   per channel-pair quadratic-form tables: pc*24 + {ww[8] | uu[8] | wu[8]}
// [192,320) BN*w_h1 (16 rows of 8)
// [320,384) w_h2 (8 rows of 8)
// [384,392) b_h2
__constant__ __align__(16) float c_all[400];
__device__ __align__(16) float g_stage[400];
__device__ float2 g_wuni[2048];   // interleaved {w_un, wd_un}

__global__ void prep(const float* __restrict__ w_un, const float* __restrict__ wd_un,
                     const float* __restrict__ w_vn, const float* __restrict__ wd_vn,
                     const float* __restrict__ w_h1, const float* __restrict__ w_h2,
                     const float* __restrict__ b_h2) {
    const float BN = 0.99999500003749968f;   // 1/sqrt(1+1e-5)
    const int i = blockIdx.x * blockDim.x + threadIdx.x;
    if (i < 2048) g_wuni[i] = make_float2(w_un[i], wd_un[i]);
    if (i < 16) {
        const int c = i, pc = c >> 1, half = c & 1;
        const int base = pc * 24;
        const float w0 = BN*w_vn[c], w1 = BN*w_vn[16+c], w2 = BN*w_vn[32+c];
        const float u0 = wd_vn[c],   u1 = wd_vn[16+c],   u2 = wd_vn[32+c];
        g_stage[base +  0 + half] = w0*w0;
        g_stage[base +  2 + half] = w1*w1;
        g_stage[base +  4 + half] = w2*w2;
        g_stage[base +  6 + half] = 2.0f*w0*w1;
        g_stage[base +  8 + half] = u0*u0;
        g_stage[base + 10 + half] = u1*u1;
        g_stage[base + 12 + half] = u2*u2;
        g_stage[base + 14 + half] = 2.0f*u0*u1;
        g_stage[base + 16 + half] = w0*u0;
        g_stage[base + 18 + half] = w1*u1;
        g_stage[base + 20 + half] = w2*u2;
        g_stage[base + 22 + half] = w0*u1 + w1*u0;
    }
    if (i >= 64 && i < 192)  g_stage[192 + (i - 64)]  = BN * w_h1[i - 64];
    if (i >= 192 && i < 256) g_stage[320 + (i - 192)] = w_h2[i - 192];
    if (i >= 256 && i < 264) g_stage[384 + (i - 256)] = b_h2[i - 256];
}

__device__ __forceinline__ u64 pk2(float x, float y) {
    u64 r; asm("mov.b64 %0,{%1,%2};" : "=l"(r) : "f"(x), "f"(y)); return r;
}
__device__ __forceinline__ void upk2(u64 v, float& x, float& y) {
    asm("mov.b64 {%0,%1},%2;" : "=f"(x), "=f"(y) : "l"(v));
}
__device__ __forceinline__ u64 fma2(u64 a, u64 b, u64 c) {
    u64 d; asm("fma.rn.f32x2 %0,%1,%2,%3;" : "=l"(d) : "l"(a), "l"(b), "l"(c)); return d;
}
__device__ __forceinline__ u64 mul2(u64 a, u64 b) {
    u64 d; asm("mul.rn.f32x2 %0,%1,%2;" : "=l"(d) : "l"(a), "l"(b)); return d;
}
__device__ __forceinline__ u64 add2(u64 a, u64 b) {
    u64 d; asm("add.rn.f32x2 %0,%1,%2;" : "=l"(d) : "l"(a), "l"(b)); return d;
}

__global__ void __launch_bounds__(128, 6) arek(
    const float* __restrict__ q_pts, const float* __restrict__ s_pts,
    const int*   __restrict__ nbr,
    const float* __restrict__ wb,
    const float* __restrict__ wd_relu,
    float* __restrict__ out, int N)
{
    const float BN = 0.99999500003749968f;   // 1/sqrt(1+1e-5)

    __shared__ __align__(16) u64 s_local2[WARPS][16][10];  // comps 0..8 = p,c,r xyz
    __shared__ __align__(16) u64 s_score2[WARPS][16][10];  // comps 0..7 = scores (unnormalized)
    __shared__ u64 s_feat2 [WARPS][32][3];                 // [h][comp] -> (p0,p1)

    const int tid = threadIdx.x;
    const int warp = tid >> 5, lane = tid & 31;
    const int n0 = blockIdx.x * (WARPS * PTS) + warp * PTS;
    if (n0 >= N) return;

    const int pp = lane >> 4;            // point within pair
    const int k  = lane & 15;            // neighbor
    int n_pt = n0 + pp;
    if (n_pt >= N) n_pt = N - 1;
    const float qx = q_pts[n_pt*3+0], qy = q_pts[n_pt*3+1], qz = q_pts[n_pt*3+2];
    const int idx = nbr[n_pt*16 + k];

    // ================= Phase 1: lane = (p, k), Gram-matrix quadratic forms =================
    {
        const float px = s_pts[idx*3+0] - qx;
        const float py = s_pts[idx*3+1] - qy;
        const float pz = s_pts[idx*3+2] - qz;

        float sx = px, sy = py, sz = pz;
        #pragma unroll
        for (int off = 1; off < 16; off <<= 1) {
            sx += __shfl_xor_sync(FULLMASK, sx, off);
            sy += __shfl_xor_sync(FULLMASK, sy, off);
            sz += __shfl_xor_sync(FULLMASK, sz, off);
        }
        const float cx = sx * (1.0f/16.0f);
        const float cy = sy * (1.0f/16.0f);
        const float cz = sz * (1.0f/16.0f);

        const float rx = py*cz - pz*cy;
        const float ry = pz*cx - px*cz;
        const float rz = px*cy - py*cx;

        ((float*)&s_local2[warp][k][0])[pp] = px;
        ((float*)&s_local2[warp][k][1])[pp] = py;
        ((float*)&s_local2[warp][k][2])[pp] = pz;
        ((float*)&s_local2[warp][k][3])[pp] = cx;
        ((float*)&s_local2[warp][k][4])[pp] = cy;
        ((float*)&s_local2[warp][k][5])[pp] = cz;
        ((float*)&s_local2[warp][k][6])[pp] = rx;
        ((float*)&s_local2[warp][k][7])[pp] = ry;
        ((float*)&s_local2[warp][k][8])[pp] = rz;

        // Gram matrix of [P, C, R]; R = P x C orthogonal to P,C -> 4 nonzero entries
        const float G00 = px*px + py*py + pz*pz;
        const float G11 = cx*cx + cy*cy + cz*cz;
        const float G22 = rx*rx + ry*ry + rz*rz;
        const float G01 = px*cx + py*cy + pz*cz;
        const u64 g00 = pk2(G00, G00), g11 = pk2(G11, G11);
        const u64 g22 = pk2(G22, G22), g01 = pk2(G01, G01);

        // h1 accum over o-pairs; channel loop packed over (2pc, 2pc+1)
        u64 h1p[4] = {0,0,0,0};
        #pragma unroll
        for (int pc = 0; pc < 8; pc++) {
            const u64* cw = (const u64*)&c_all[pc*24];
            const u64 pp2 = fma2(g00, cw[0], fma2(g11, cw[1], fma2(g22, cw[2],  mul2(g01, cw[3]))));
            const u64 dq2 = fma2(g00, cw[4], fma2(g11, cw[5], fma2(g22, cw[6],  mul2(g01, cw[7]))));
            const u64 dt2 = fma2(g00, cw[8], fma2(g11, cw[9], fma2(g22, cw[10], mul2(g01, cw[11]))));
            float dta, dtb, dqa, dqb;
            upk2(dt2, dta, dtb); upk2(dq2, dqa, dqb);
            const float nfa = (dta >= 0.0f) ? 0.0f : (-0.8f * __fdividef(dta, dqa + 1e-6f));
            const float nfb = (dtb >= 0.0f) ? 0.0f : (-0.8f * __fdividef(dtb, dqb + 1e-6f));
            const u64 nf = pk2(nfa, nfb);
            // |s|^2 = pp + nf*(2*dt + nf*dq)
            const u64 dd2   = add2(dt2, dt2);
            const u64 inner = fma2(nf, dq2, dd2);
            const u64 snsq  = fma2(nf, inner, pp2);
            float na, nb; upk2(snsq, na, nb);
            const float sa = sqrtf(fmaxf(na, 0.0f));
            const float sb = sqrtf(fmaxf(nb, 0.0f));
            const u64 SA = pk2(sa, sa), SB = pk2(sb, sb);
            const ulonglong2 r0a = *(const ulonglong2*)&c_all[192 + (2*pc  )*8];
            const ulonglong2 r0b = *(const ulonglong2*)&c_all[192 + (2*pc  )*8 + 4];
            const ulonglong2 r1a = *(const ulonglong2*)&c_all[192 + (2*pc+1)*8];
            const ulonglong2 r1b = *(const ulonglong2*)&c_all[192 + (2*pc+1)*8 + 4];
            h1p[0] = fma2(SA, r0a.x, fma2(SB, r1a.x, h1p[0]));
            h1p[1] = fma2(SA, r0a.y, fma2(SB, r1a.y, h1p[1]));
            h1p[2] = fma2(SA, r0b.x, fma2(SB, r1b.x, h1p[2]));
            h1p[3] = fma2(SA, r0b.y, fma2(SB, r1b.y, h1p[3]));
        }
        float h1s[8];
        #pragma unroll
        for (int o2 = 0; o2 < 4; o2++) {
            float ea, eb; upk2(h1p[o2], ea, eb);   // BN folded into w_h1 table
            h1s[2*o2]   = fmaxf(0.0f, ea);
            h1s[2*o2+1] = fmaxf(0.0f, eb);
        }

        // h2 accum over o-pairs
        u64 h2p[4] = { *(const u64*)&c_all[384], *(const u64*)&c_all[386],
                       *(const u64*)&c_all[388], *(const u64*)&c_all[390] };
        #pragma unroll
        for (int c = 0; c < 8; c++) {
            const ulonglong2 wa  = *(const ulonglong2*)&c_all[320 + c*8];
            const ulonglong2 wbq = *(const ulonglong2*)&c_all[320 + c*8 + 4];
            const u64 SC = pk2(h1s[c], h1s[c]);
            h2p[0] = fma2(SC, wa.x,  h2p[0]);
            h2p[1] = fma2(SC, wa.y,  h2p[1]);
            h2p[2] = fma2(SC, wbq.x, h2p[2]);
            h2p[3] = fma2(SC, wbq.y, h2p[3]);
        }
        float h2[8];
        upk2(h2p[0], h2[0], h2[1]); upk2(h2p[1], h2[2], h2[3]);
        upk2(h2p[2], h2[4], h2[5]); upk2(h2p[3], h2[6], h2[7]);
        // softmax scale + shift cancel in phase-2 per-k normalization;
        // subtract h2[0] for range safety; score[0] == 1 exploited in phase 2.
        const float m = h2[0];
        ((float*)&s_score2[warp][k][0])[pp] = 1.0f;
        #pragma unroll
        for (int o = 1; o < 8; o++)
            ((float*)&s_score2[warp][k][o])[pp] = __expf(h2[o] - m);
    }
    __syncwarp();

    // ======= Phase 2: correlation, lane = channel h; wb via coalesced __ldg =======
    u64 wbd0[8], wbd1[8], wbd2[8];
    #pragma unroll
    for (int ks = 0; ks < 8; ks++) {
        const float w0 = __ldg(wb +       ks*32 + lane);
        const float w1 = __ldg(wb + 256 + ks*32 + lane);
        const float w2 = __ldg(wb + 512 + ks*32 + lane);
        wbd0[ks] = pk2(w0, w0); wbd1[ks] = pk2(w1, w1); wbd2[ks] = pk2(w2, w2);
    }
    {
        u64 fa0 = 0, fa1 = 0, fa2 = 0;
        #pragma unroll
        for (int kk = 0; kk < 16; kk++) {
            const ulonglong2* scv = (const ulonglong2*)s_score2[warp][kk];
            const ulonglong2 sAB = scv[0], sCD = scv[1], sEF = scv[2], sGH = scv[3];
            // score[0] == 1: init accumulators with wbd[0] directly
            u64 we0 = fma2(sAB.y, wbd0[1], wbd0[0]);
            u64 we1 = fma2(sAB.y, wbd1[1], wbd1[0]);
            u64 we2 = fma2(sAB.y, wbd2[1], wbd2[0]);
            we0 = fma2(sCD.x, wbd0[2], we0); we1 = fma2(sCD.x, wbd1[2], we1); we2 = fma2(sCD.x, wbd2[2], we2);
            we0 = fma2(sCD.y, wbd0[3], we0); we1 = fma2(sCD.y, wbd1[3], we1); we2 = fma2(sCD.y, wbd2[3], we2);
            we0 = fma2(sEF.x, wbd0[4], we0); we1 = fma2(sEF.x, wbd1[4], we1); we2 = fma2(sEF.x, wbd2[4], we2);
            we0 = fma2(sEF.y, wbd0[5], we0); we1 = fma2(sEF.y, wbd1[5], we1); we2 = fma2(sEF.y, wbd2[5], we2);
            we0 = fma2(sGH.x, wbd0[6], we0); we1 = fma2(sGH.x, wbd1[6], we1); we2 = fma2(sGH.x, wbd2[6], we2);
            we0 = fma2(sGH.y, wbd0[7], we0); we1 = fma2(sGH.y, wbd1[7], we1); we2 = fma2(sGH.y, wbd2[7], we2);

            const ulonglong2* Lv = (const ulonglong2*)s_local2[warp][kk];
            const ulonglong2 L01 = Lv[0], L23 = Lv[1], L45 = Lv[2], L67 = Lv[3];
            const u64 L8 = s_local2[warp][kk][8];
            const u64 q0 = fma2(L01.x, we0, fma2(L23.y, we1, mul2(L67.x, we2)));
            const u64 q1 = fma2(L01.y, we0, fma2(L45.x, we1, mul2(L67.y, we2)));
            const u64 q2 = fma2(L23.x, we0, fma2(L45.y, we1, mul2(L8,    we2)));
            const u64 nn = fma2(q0, q0, fma2(q1, q1, mul2(q2, q2)));
            float n0f, n1f; upk2(nn, n0f, n1f);
            const u64 iv = pk2(rsqrtf(fmaxf(n0f, 1e-24f)), rsqrtf(fmaxf(n1f, 1e-24f)));
            fa0 = fma2(q0, iv, fa0);
            fa1 = fma2(q1, iv, fa1);
            fa2 = fma2(q2, iv, fa2);
        }
        const u64 SC = pk2(1.0f/16.0f, 1.0f/16.0f);
        s_feat2[warp][lane][0] = mul2(fa0, SC);
        s_feat2[warp][lane][1] = mul2(fa1, SC);
        s_feat2[warp][lane][2] = mul2(fa2, SC);
    }
    __syncwarp();

    // ======= Phase 3a: VNLeakyReLU(32->32), packed over points =======
    {
        u64 f0 = s_feat2[warp][lane][0];
        u64 f1 = s_feat2[warp][lane][1];
        u64 f2 = s_feat2[warp][lane][2];
        u64 g0 = 0, g1 = 0, g2 = 0;
        #pragma unroll
        for (int h = 0; h < 32; h++) {
            const float w = __ldg(wd_relu + h*32 + lane);
            const u64 w2 = pk2(w, w);
            g0 = fma2(s_feat2[warp][h][0], w2, g0);
            g1 = fma2(s_feat2[warp][h][1], w2, g1);
            g2 = fma2(s_feat2[warp][h][2], w2, g2);
        }
        const u64 dot2 = fma2(f0, g0, fma2(f1, g1, mul2(f2, g2)));
        const u64 dsq2 = fma2(g0, g0, fma2(g1, g1, mul2(g2, g2)));
        float dta, dtb, dqa, dqb;
        upk2(dot2, dta, dtb); upk2(dsq2, dqa, dqb);
        const float nfa = (dta >= 0.0f) ? 0.0f : (-0.8f * __fdividef(dta, dqa + 1e-6f));
        const float nfb = (dtb >= 0.0f) ? 0.0f : (-0.8f * __fdividef(dtb, dqb + 1e-6f));
        const u64 nf = pk2(nfa, nfb);
        __syncwarp();
        s_feat2[warp][lane][0] = fma2(nf, g0, f0);
        s_feat2[warp][lane][1] = fma2(nf, g1, f1);
        s_feat2[warp][lane][2] = fma2(nf, g2, f2);
    }
    __syncwarp();

    // ======= Phase 3b: VNLinearLeakyReLU(32->64), interleaved weights, packed =======
    {
        u64 ax=0, ay=0, az=0, bx=0, by=0, bz=0;   // j = lane
        u64 Ax=0, Ay=0, Az=0, Bx=0, By=0, Bz=0;   // j = lane + 32
        #pragma unroll
        for (int h = 0; h < 32; h++) {
            const float2 wv0 = g_wuni[h*64 + lane];
            const float2 wv1 = g_wuni[h*64 + lane + 32];
            const u64 F0 = s_feat2[warp][h][0];
            const u64 F1 = s_feat2[warp][h][1];
            const u64 F2 = s_feat2[warp][h][2];
            const u64 wa0d = pk2(wv0.x, wv0.x), wd0d = pk2(wv0.y, wv0.y);
            const u64 wa1d = pk2(wv1.x, wv1.x), wd1d = pk2(wv1.y, wv1.y);
            ax = fma2(F0, wa0d, ax); ay = fma2(F1, wa0d, ay); az = fma2(F2, wa0d, az);
            bx = fma2(F0, wd0d, bx); by = fma2(F1, wd0d, by); bz = fma2(F2, wd0d, bz);
            Ax = fma2(F0, wa1d, Ax); Ay = fma2(F1, wa1d, Ay); Az = fma2(F2, wa1d, Az);
            Bx = fma2(F0, wd1d, Bx); By = fma2(F1, wd1d, By); Bz = fma2(F2, wd1d, Bz);
        }
        float axp[2], ayp[2], azp[2], bxp[2], byp[2], bzp[2];
        float Axp[2], Ayp[2], Azp[2], Bxp[2], Byp[2], Bzp[2];
        upk2(ax, axp[0], axp[1]); upk2(ay, ayp[0], ayp[1]); upk2(az, azp[0], azp[1]);
        upk2(bx, bxp[0], bxp[1]); upk2(by, byp[0], byp[1]); upk2(bz, bzp[0], bzp[1]);
        upk2(Ax, Axp[0], Axp[1]); upk2(Ay, Ayp[0], Ayp[1]); upk2(Az, Azp[0], Azp[1]);
        upk2(Bx, Bxp[0], Bxp[1]); upk2(By, Byp[0], Byp[1]); upk2(Bz, Bzp[0], Bzp[1]);
        #pragma unroll
        for (int p = 0; p < PTS; p++) {
            if (n0 + p >= N) break;
            const int n = n0 + p;
            {
                const int j = lane;
                const float x0 = BN*axp[p], x1 = BN*ayp[p], x2 = BN*azp[p];
                const float dt = x0*bxp[p] + x1*byp[p] + x2*bzp[p];
                const float dq = bxp[p]*bxp[p] + byp[p]*byp[p] + bzp[p]*bzp[p];
                const float fc = (dt >= 0.0f) ? 0.0f : (0.8f * __fdividef(dt, dq + 1e-6f));
                out[n*192 + j*3 + 0] = x0 - fc*bxp[p];
                out[n*192 + j*3 + 1] = x1 - fc*byp[p];
                out[n*192 + j*3 + 2] = x2 - fc*bzp[p];
            }
            {
                const int j = lane + 32;
                const float x0 = BN*Axp[p], x1 = BN*Ayp[p], x2 = BN*Azp[p];
                const float dt = x0*Bxp[p] + x1*Byp[p] + x2*Bzp[p];
                const float dq = Bxp[p]*Bxp[p] + Byp[p]*Byp[p] + Bzp[p]*Bzp[p];
                const float fc = (dt >= 0.0f) ? 0.0f : (0.8f * __fdividef(dt, dq + 1e-6f));
                out[n*192 + j*3 + 0] = x0 - fc*Bxp[p];
                out[n*192 + j*3 + 1] = x1 - fc*Byp[p];
                out[n*192 + j*3 + 2] = x2 - fc*Bzp[p];
            }
        }
    }
}

extern "C" void kernel_launch(void* const* d_in, const int* in_sizes, int n_in,
                              void* d_out, int out_size) {
    const float* q_pts   = (const float*)d_in[0];
    const float* s_pts   = (const float*)d_in[1];
    const int*   nbr     = (const int*)  d_in[3];
    const float* wb      = (const float*)d_in[4];
    const float* w_vn    = (const float*)d_in[5];
    const float* wd_vn   = (const float*)d_in[6];
    const float* w_h1    = (const float*)d_in[7];
    const float* w_h2    = (const float*)d_in[8];
    const float* b_h2    = (const float*)d_in[9];
    const float* wd_relu = (const float*)d_in[10];
    const float* w_un    = (const float*)d_in[11];
    const float* wd_un   = (const float*)d_in[12];

    prep<<<8, 256>>>(w_un, wd_un, w_vn, wd_vn, w_h1, w_h2, b_h2);

    void* stage_ptr = nullptr;
    cudaGetSymbolAddress(&stage_ptr, g_stage);
    cudaMemcpyToSymbolAsync(c_all, stage_ptr, 392 * sizeof(float), 0,
                            cudaMemcpyDeviceToDevice, 0);

    const int N = in_sizes[0] / 3;
    const int per_block = WARPS * PTS;
    const int blocks = (N + per_block - 1) / per_block;
    arek<<<blocks, 128>>>(q_pts, s_pts, nbr, wb, wd_relu, (float*)d_out, N);
}

// round 17
// speedup vs baseline: 1.0617x; 1.0617x over previous
#include <cuda_runtime.h>

typedef unsigned long long u64;
#define WARPS 4
#define PTS 2
#define FULLMASK 0xffffffffu

// constant bank layout (floats):
// [0,192)   per channel-pair quadratic-form tables: pc*24 + {ww[8] | uu[8] | wu[8]}
// [192,320) BN*w_h1 (16 rows of 8)
// [320,384) w_h2 (8 rows of 8)
// [384,392) b_h2
__constant__ __align__(16) float c_all[400];
__device__ float2 g_wuni[2048];   // interleaved {w_un, wd_un}

// prep writes DIRECTLY into the constant bank via its device address
// (same memory + same kernel-boundary ordering as the cudaMemcpyToSymbol
// path used previously; removes one graph node).
__global__ void prep(float* __restrict__ cdst,
                     const float* __restrict__ w_un, const float* __restrict__ wd_un,
                     const float* __restrict__ w_vn, const float* __restrict__ wd_vn,
                     const float* __restrict__ w_h1, const float* __restrict__ w_h2,
                     const float* __restrict__ b_h2) {
    const float BN = 0.99999500003749968f;   // 1/sqrt(1+1e-5)
    const int i = blockIdx.x * blockDim.x + threadIdx.x;
    if (i < 2048) g_wuni[i] = make_float2(w_un[i], wd_un[i]);
    if (i < 16) {
        const int c = i, pc = c >> 1, half = c & 1;
        const int base = pc * 24;
        const float w0 = BN*w_vn[c], w1 = BN*w_vn[16+c], w2 = BN*w_vn[32+c];
        const float u0 = wd_vn[c],   u1 = wd_vn[16+c],   u2 = wd_vn[32+c];
        cdst[base +  0 + half] = w0*w0;
        cdst[base +  2 + half] = w1*w1;
        cdst[base +  4 + half] = w2*w2;
        cdst[base +  6 + half] = 2.0f*w0*w1;
        cdst[base +  8 + half] = u0*u0;
        cdst[base + 10 + half] = u1*u1;
        cdst[base + 12 + half] = u2*u2;
        cdst[base + 14 + half] = 2.0f*u0*u1;
        cdst[base + 16 + half] = w0*u0;
        cdst[base + 18 + half] = w1*u1;
        cdst[base + 20 + half] = w2*u2;
        cdst[base + 22 + half] = w0*u1 + w1*u0;
    }
    if (i >= 64 && i < 192)  cdst[192 + (i - 64)]  = BN * w_h1[i - 64];
    if (i >= 192 && i < 256) cdst[320 + (i - 192)] = w_h2[i - 192];
    if (i >= 256 && i < 264) cdst[384 + (i - 256)] = b_h2[i - 256];
}

__device__ __forceinline__ u64 pk2(float x, float y) {
    u64 r; asm("mov.b64 %0,{%1,%2};" : "=l"(r) : "f"(x), "f"(y)); return r;
}
__device__ __forceinline__ void upk2(u64 v, float& x, float& y) {
    asm("mov.b64 {%0,%1},%2;" : "=f"(x), "=f"(y) : "l"(v));
}
__device__ __forceinline__ u64 fma2(u64 a, u64 b, u64 c) {
    u64 d; asm("fma.rn.f32x2 %0,%1,%2,%3;" : "=l"(d) : "l"(a), "l"(b), "l"(c)); return d;
}
__device__ __forceinline__ u64 mul2(u64 a, u64 b) {
    u64 d; asm("mul.rn.f32x2 %0,%1,%2;" : "=l"(d) : "l"(a), "l"(b)); return d;
}
__device__ __forceinline__ u64 add2(u64 a, u64 b) {
    u64 d; asm("add.rn.f32x2 %0,%1,%2;" : "=l"(d) : "l"(a), "l"(b)); return d;
}

__global__ void __launch_bounds__(128, 6) arek(
    const float* __restrict__ q_pts, const float* __restrict__ s_pts,
    const int*   __restrict__ nbr,
    const float* __restrict__ wb,
    const float* __restrict__ wd_relu,
    float* __restrict__ out, int N)
{
    const float BN = 0.99999500003749968f;   // 1/sqrt(1+1e-5)

    __shared__ __align__(16) u64 s_local2[WARPS][16][10];  // comps 0..8 = p,c,r xyz
    __shared__ __align__(16) u64 s_score2[WARPS][16][10];  // comps 0..7 = scores (unnormalized)
    __shared__ u64 s_feat2 [WARPS][32][3];                 // [h][comp] -> (p0,p1)

    const int tid = threadIdx.x;
    const int warp = tid >> 5, lane = tid & 31;
    const int n0 = blockIdx.x * (WARPS * PTS) + warp * PTS;
    if (n0 >= N) return;

    const int pp = lane >> 4;            // point within pair
    const int k  = lane & 15;            // neighbor
    int n_pt = n0 + pp;
    if (n_pt >= N) n_pt = N - 1;
    const float qx = q_pts[n_pt*3+0], qy = q_pts[n_pt*3+1], qz = q_pts[n_pt*3+2];
    const int idx = nbr[n_pt*16 + k];

    // ================= Phase 1: lane = (p, k), Gram-matrix quadratic forms =================
    {
        const float px = s_pts[idx*3+0] - qx;
        const float py = s_pts[idx*3+1] - qy;
        const float pz = s_pts[idx*3+2] - qz;

        float sx = px, sy = py, sz = pz;
        #pragma unroll
        for (int off = 1; off < 16; off <<= 1) {
            sx += __shfl_xor_sync(FULLMASK, sx, off);
            sy += __shfl_xor_sync(FULLMASK, sy, off);
            sz += __shfl_xor_sync(FULLMASK, sz, off);
        }
        const float cx = sx * (1.0f/16.0f);
        const float cy = sy * (1.0f/16.0f);
        const float cz = sz * (1.0f/16.0f);

        const float rx = py*cz - pz*cy;
        const float ry = pz*cx - px*cz;
        const float rz = px*cy - py*cx;

        ((float*)&s_local2[warp][k][0])[pp] = px;
        ((float*)&s_local2[warp][k][1])[pp] = py;
        ((float*)&s_local2[warp][k][2])[pp] = pz;
        ((float*)&s_local2[warp][k][3])[pp] = cx;
        ((float*)&s_local2[warp][k][4])[pp] = cy;
        ((float*)&s_local2[warp][k][5])[pp] = cz;
        ((float*)&s_local2[warp][k][6])[pp] = rx;
        ((float*)&s_local2[warp][k][7])[pp] = ry;
        ((float*)&s_local2[warp][k][8])[pp] = rz;

        // Gram matrix of [P, C, R]; R = P x C orthogonal to P,C -> 4 nonzero entries
        const float G00 = px*px + py*py + pz*pz;
        const float G11 = cx*cx + cy*cy + cz*cz;
        const float G22 = rx*rx + ry*ry + rz*rz;
        const float G01 = px*cx + py*cy + pz*cz;
        const u64 g00 = pk2(G00, G00), g11 = pk2(G11, G11);
        const u64 g22 = pk2(G22, G22), g01 = pk2(G01, G01);

        // h1 accum over o-pairs; channel loop packed over (2pc, 2pc+1)
        u64 h1p[4] = {0,0,0,0};
        #pragma unroll
        for (int pc = 0; pc < 8; pc++) {
            const u64* cw = (const u64*)&c_all[pc*24];
            const u64 pp2 = fma2(g00, cw[0], fma2(g11, cw[1], fma2(g22, cw[2],  mul2(g01, cw[3]))));
            const u64 dq2 = fma2(g00, cw[4], fma2(g11, cw[5], fma2(g22, cw[6],  mul2(g01, cw[7]))));
            const u64 dt2 = fma2(g00, cw[8], fma2(g11, cw[9], fma2(g22, cw[10], mul2(g01, cw[11]))));
            float dta, dtb, dqa, dqb;
            upk2(dt2, dta, dtb); upk2(dq2, dqa, dqb);
            const float nfa = (dta >= 0.0f) ? 0.0f : (-0.8f * __fdividef(dta, dqa + 1e-6f));
            const float nfb = (dtb >= 0.0f) ? 0.0f : (-0.8f * __fdividef(dtb, dqb + 1e-6f));
            const u64 nf = pk2(nfa, nfb);
            // |s|^2 = pp + nf*(2*dt + nf*dq)
            const u64 dd2   = add2(dt2, dt2);
            const u64 inner = fma2(nf, dq2, dd2);
            const u64 snsq  = fma2(nf, inner, pp2);
            float na, nb; upk2(snsq, na, nb);
            const float sa = sqrtf(fmaxf(na, 0.0f));
            const float sb = sqrtf(fmaxf(nb, 0.0f));
            const u64 SA = pk2(sa, sa), SB = pk2(sb, sb);
            const ulonglong2 r0a = *(const ulonglong2*)&c_all[192 + (2*pc  )*8];
            const ulonglong2 r0b = *(const ulonglong2*)&c_all[192 + (2*pc  )*8 + 4];
            const ulonglong2 r1a = *(const ulonglong2*)&c_all[192 + (2*pc+1)*8];
            const ulonglong2 r1b = *(const ulonglong2*)&c_all[192 + (2*pc+1)*8 + 4];
            h1p[0] = fma2(SA, r0a.x, fma2(SB, r1a.x, h1p[0]));
            h1p[1] = fma2(SA, r0a.y, fma2(SB, r1a.y, h1p[1]));
            h1p[2] = fma2(SA, r0b.x, fma2(SB, r1b.x, h1p[2]));
            h1p[3] = fma2(SA, r0b.y, fma2(SB, r1b.y, h1p[3]));
        }
        float h1s[8];
        #pragma unroll
        for (int o2 = 0; o2 < 4; o2++) {
            float ea, eb; upk2(h1p[o2], ea, eb);   // BN folded into w_h1 table
            h1s[2*o2]   = fmaxf(0.0f, ea);
            h1s[2*o2+1] = fmaxf(0.0f, eb);
        }

        // h2 accum over o-pairs
        u64 h2p[4] = { *(const u64*)&c_all[384], *(const u64*)&c_all[386],
                       *(const u64*)&c_all[388], *(const u64*)&c_all[390] };
        #pragma unroll
        for (int c = 0; c < 8; c++) {
            const ulonglong2 wa  = *(const ulonglong2*)&c_all[320 + c*8];
            const ulonglong2 wbq = *(const ulonglong2*)&c_all[320 + c*8 + 4];
            const u64 SC = pk2(h1s[c], h1s[c]);
            h2p[0] = fma2(SC, wa.x,  h2p[0]);
            h2p[1] = fma2(SC, wa.y,  h2p[1]);
            h2p[2] = fma2(SC, wbq.x, h2p[2]);
            h2p[3] = fma2(SC, wbq.y, h2p[3]);
        }
        float h2[8];
        upk2(h2p[0], h2[0], h2[1]); upk2(h2p[1], h2[2], h2[3]);
        upk2(h2p[2], h2[4], h2[5]); upk2(h2p[3], h2[6], h2[7]);
        // softmax scale + shift cancel in phase-2 per-k normalization;
        // subtract h2[0] for range safety; score[0] == 1 exploited in phase 2.
        const float m = h2[0];
        ((float*)&s_score2[warp][k][0])[pp] = 1.0f;
        #pragma unroll
        for (int o = 1; o < 8; o++)
            ((float*)&s_score2[warp][k][o])[pp] = __expf(h2[o] - m);
    }
    __syncwarp();

    // ======= Phase 2: correlation, lane = channel h; wb via coalesced __ldg =======
    u64 wbd0[8], wbd1[8], wbd2[8];
    #pragma unroll
    for (int ks = 0; ks < 8; ks++) {
        const float w0 = __ldg(wb +       ks*32 + lane);
        const float w1 = __ldg(wb + 256 + ks*32 + lane);
        const float w2 = __ldg(wb + 512 + ks*32 + lane);
        wbd0[ks] = pk2(w0, w0); wbd1[ks] = pk2(w1, w1); wbd2[ks] = pk2(w2, w2);
    }
    {
        u64 fa0 = 0, fa1 = 0, fa2 = 0;
        #pragma unroll
        for (int kk = 0; kk < 16; kk++) {
            const ulonglong2* scv = (const ulonglong2*)s_score2[warp][kk];
            const ulonglong2 sAB = scv[0], sCD = scv[1], sEF = scv[2], sGH = scv[3];
            // score[0] == 1: init accumulators with wbd[0] directly
            u64 we0 = fma2(sAB.y, wbd0[1], wbd0[0]);
            u64 we1 = fma2(sAB.y, wbd1[1], wbd1[0]);
            u64 we2 = fma2(sAB.y, wbd2[1], wbd2[0]);
            we0 = fma2(sCD.x, wbd0[2], we0); we1 = fma2(sCD.x, wbd1[2], we1); we2 = fma2(sCD.x, wbd2[2], we2);
            we0 = fma2(sCD.y, wbd0[3], we0); we1 = fma2(sCD.y, wbd1[3], we1); we2 = fma2(sCD.y, wbd2[3], we2);
            we0 = fma2(sEF.x, wbd0[4], we0); we1 = fma2(sEF.x, wbd1[4], we1); we2 = fma2(sEF.x, wbd2[4], we2);
            we0 = fma2(sEF.y, wbd0[5], we0); we1 = fma2(sEF.y, wbd1[5], we1); we2 = fma2(sEF.y, wbd2[5], we2);
            we0 = fma2(sGH.x, wbd0[6], we0); we1 = fma2(sGH.x, wbd1[6], we1); we2 = fma2(sGH.x, wbd2[6], we2);
            we0 = fma2(sGH.y, wbd0[7], we0); we1 = fma2(sGH.y, wbd1[7], we1); we2 = fma2(sGH.y, wbd2[7], we2);

            const ulonglong2* Lv = (const ulonglong2*)s_local2[warp][kk];
            const ulonglong2 L01 = Lv[0], L23 = Lv[1], L45 = Lv[2], L67 = Lv[3];
            const u64 L8 = s_local2[warp][kk][8];
            const u64 q0 = fma2(L01.x, we0, fma2(L23.y, we1, mul2(L67.x, we2)));
            const u64 q1 = fma2(L01.y, we0, fma2(L45.x, we1, mul2(L67.y, we2)));
            const u64 q2 = fma2(L23.x, we0, fma2(L45.y, we1, mul2(L8,    we2)));
            const u64 nn = fma2(q0, q0, fma2(q1, q1, mul2(q2, q2)));
            float n0f, n1f; upk2(nn, n0f, n1f);
            const u64 iv = pk2(rsqrtf(fmaxf(n0f, 1e-24f)), rsqrtf(fmaxf(n1f, 1e-24f)));
            fa0 = fma2(q0, iv, fa0);
            fa1 = fma2(q1, iv, fa1);
            fa2 = fma2(q2, iv, fa2);
        }
        const u64 SC = pk2(1.0f/16.0f, 1.0f/16.0f);
        s_feat2[warp][lane][0] = mul2(fa0, SC);
        s_feat2[warp][lane][1] = mul2(fa1, SC);
        s_feat2[warp][lane][2] = mul2(fa2, SC);
    }
    __syncwarp();

    // ======= Phase 3a: VNLeakyReLU(32->32), packed over points =======
    {
        u64 f0 = s_feat2[warp][lane][0];
        u64 f1 = s_feat2[warp][lane][1];
        u64 f2 = s_feat2[warp][lane][2];
        u64 g0 = 0, g1 = 0, g2 = 0;
        #pragma unroll
        for (int h = 0; h < 32; h++) {
            const float w = __ldg(wd_relu + h*32 + lane);
            const u64 w2 = pk2(w, w);
            g0 = fma2(s_feat2[warp][h][0], w2, g0);
            g1 = fma2(s_feat2[warp][h][1], w2, g1);
            g2 = fma2(s_feat2[warp][h][2], w2, g2);
        }
        const u64 dot2 = fma2(f0, g0, fma2(f1, g1, mul2(f2, g2)));
        const u64 dsq2 = fma2(g0, g0, fma2(g1, g1, mul2(g2, g2)));
        float dta, dtb, dqa, dqb;
        upk2(dot2, dta, dtb); upk2(dsq2, dqa, dqb);
        const float nfa = (dta >= 0.0f) ? 0.0f : (-0.8f * __fdividef(dta, dqa + 1e-6f));
        const float nfb = (dtb >= 0.0f) ? 0.0f : (-0.8f * __fdividef(dtb, dqb + 1e-6f));
        const u64 nf = pk2(nfa, nfb);
        __syncwarp();
        s_feat2[warp][lane][0] = fma2(nf, g0, f0);
        s_feat2[warp][lane][1] = fma2(nf, g1, f1);
        s_feat2[warp][lane][2] = fma2(nf, g2, f2);
    }
    __syncwarp();

    // ======= Phase 3b: VNLinearLeakyReLU(32->64), interleaved weights, packed =======
    {
        u64 ax=0, ay=0, az=0, bx=0, by=0, bz=0;   // j = lane
        u64 Ax=0, Ay=0, Az=0, Bx=0, By=0, Bz=0;   // j = lane + 32
        #pragma unroll
        for (int h = 0; h < 32; h++) {
            const float2 wv0 = g_wuni[h*64 + lane];
            const float2 wv1 = g_wuni[h*64 + lane + 32];
            const u64 F0 = s_feat2[warp][h][0];
            const u64 F1 = s_feat2[warp][h][1];
            const u64 F2 = s_feat2[warp][h][2];
            const u64 wa0d = pk2(wv0.x, wv0.x), wd0d = pk2(wv0.y, wv0.y);
            const u64 wa1d = pk2(wv1.x, wv1.x), wd1d = pk2(wv1.y, wv1.y);
            ax = fma2(F0, wa0d, ax); ay = fma2(F1, wa0d, ay); az = fma2(F2, wa0d, az);
            bx = fma2(F0, wd0d, bx); by = fma2(F1, wd0d, by); bz = fma2(F2, wd0d, bz);
            Ax = fma2(F0, wa1d, Ax); Ay = fma2(F1, wa1d, Ay); Az = fma2(F2, wa1d, Az);
            Bx = fma2(F0, wd1d, Bx); By = fma2(F1, wd1d, By); Bz = fma2(F2, wd1d, Bz);
        }
        float axp[2], ayp[2], azp[2], bxp[2], byp[2], bzp[2];
        float Axp[2], Ayp[2], Azp[2], Bxp[2], Byp[2], Bzp[2];
        upk2(ax, axp[0], axp[1]); upk2(ay, ayp[0], ayp[1]); upk2(az, azp[0], azp[1]);
        upk2(bx, bxp[0], bxp[1]); upk2(by, byp[0], byp[1]); upk2(bz, bzp[0], bzp[1]);
        upk2(Ax, Axp[0], Axp[1]); upk2(Ay, Ayp[0], Ayp[1]); upk2(Az, Azp[0], Azp[1]);
        upk2(Bx, Bxp[0], Bxp[1]); upk2(By, Byp[0], Byp[1]); upk2(Bz, Bzp[0], Bzp[1]);
        #pragma unroll
        for (int p = 0; p < PTS; p++) {
            if (n0 + p >= N) break;
            const int n = n0 + p;
            {
                const int j = lane;
                const float x0 = BN*axp[p], x1 = BN*ayp[p], x2 = BN*azp[p];
                const float dt = x0*bxp[p] + x1*byp[p] + x2*bzp[p];
                const float dq = bxp[p]*bxp[p] + byp[p]*byp[p] + bzp[p]*bzp[p];
                const float fc = (dt >= 0.0f) ? 0.0f : (0.8f * __fdividef(dt, dq + 1e-6f));
                out[n*192 + j*3 + 0] = x0 - fc*bxp[p];
                out[n*192 + j*3 + 1] = x1 - fc*byp[p];
                out[n*192 + j*3 + 2] = x2 - fc*bzp[p];
            }
            {
                const int j = lane + 32;
                const float x0 = BN*Axp[p], x1 = BN*Ayp[p], x2 = BN*Azp[p];
                const float dt = x0*Bxp[p] + x1*Byp[p] + x2*Bzp[p];
                const float dq = Bxp[p]*Bxp[p] + Byp[p]*Byp[p] + Bzp[p]*Bzp[p];
                const float fc = (dt >= 0.0f) ? 0.0f : (0.8f * __fdividef(dt, dq + 1e-6f));
                out[n*192 + j*3 + 0] = x0 - fc*Bxp[p];
                out[n*192 + j*3 + 1] = x1 - fc*Byp[p];
                out[n*192 + j*3 + 2] = x2 - fc*Bzp[p];
            }
        }
    }
}

extern "C" void kernel_launch(void* const* d_in, const int* in_sizes, int n_in,
                              void* d_out, int out_size) {
    const float* q_pts   = (const float*)d_in[0];
    const float* s_pts   = (const float*)d_in[1];
    const int*   nbr     = (const int*)  d_in[3];
    const float* wb      = (const float*)d_in[4];
    const float* w_vn    = (const float*)d_in[5];
    const float* wd_vn   = (const float*)d_in[6];
    const float* w_h1    = (const float*)d_in[7];
    const float* w_h2    = (const float*)d_in[8];
    const float* b_h2    = (const float*)d_in[9];
    const float* wd_relu = (const float*)d_in[10];
    const float* w_un    = (const float*)d_in[11];
    const float* wd_un   = (const float*)d_in[12];

    void* c_ptr = nullptr;
    cudaGetSymbolAddress(&c_ptr, c_all);

    prep<<<8, 256>>>((float*)c_ptr, w_un, wd_un, w_vn, wd_vn, w_h1, w_h2, b_h2);

    const int N = in_sizes[0] / 3;
    const int per_block = WARPS * PTS;
    const int blocks = (N + per_block - 1) / per_block;
    arek<<<blocks, 128>>>(q_pts, s_pts, nbr, wb, wd_relu, (float*)d_out, N);
}